// round 3
// baseline (speedup 1.0000x reference)
#include <cuda_runtime.h>
#include <cstdint>
#include <mma.h>
using namespace nvcuda;

// Problem collapses: einsum('bnqk,bnqe->bnqe', softmax(attn), v) = rowsum(softmax)*v = v
// => out = x @ (Wv @ Wproj) + (b_v @ Wproj + b_proj),  Wv = w_qkv[:, 2048:3072]

constexpr int DIMC = 1024;
constexpr int MX   = 4096;          // BATCH*SEQ
constexpr int BN = 128, BK = 32;

__device__ float g_wc[DIMC * DIMC];
__device__ float g_bc[DIMC];

__device__ __forceinline__ void cp_async16(void* smem, const void* gmem) {
    unsigned s = (unsigned)__cvta_generic_to_shared(smem);
    asm volatile("cp.async.cg.shared.global [%0], [%1], 16;\n" :: "r"(s), "l"(gmem));
}
__device__ __forceinline__ void cp_commit() { asm volatile("cp.async.commit_group;\n"); }
template<int N> __device__ __forceinline__ void cp_wait() {
    asm volatile("cp.async.wait_group %0;\n" :: "n"(N));
}

// C[M,N] = A[M,K](lda) @ B[K,N](ldb) (+bias), tf32 WMMA, 2-stage cp.async pipeline.
// 256 threads, warp grid 2x4. BM in {64,128}. Grid: (N/128, M/BM).
template<int BM>
__global__ __launch_bounds__(256) void gemm_tf32(
    const float* __restrict__ A, int lda,
    const float* __restrict__ B, int ldb,
    float* __restrict__ C, int ldc,
    const float* __restrict__ bias, int K)
{
    constexpr int WM    = BM / 2;      // 2 warp rows
    constexpr int MF    = WM / 16;     // m-fragments per warp
    constexpr int LDA_S = BK + 4;      // 36 (16B-aligned rows, conflict-free)
    constexpr int LDB_S = BN + 4;      // 132

    extern __shared__ float sm[];
    float* Asb = sm;                       // [2][BM][LDA_S]
    float* Bsb = sm + 2 * BM * LDA_S;      // [2][BK][LDB_S]

    const int tid  = threadIdx.x;
    const int wid  = tid >> 5;
    const int lane = tid & 31;
    const int wrow = wid >> 2;             // 0..1
    const int wcol = wid & 3;              // 0..3
    const int bm   = blockIdx.y * BM;
    const int bn   = blockIdx.x * BN;

    wmma::fragment<wmma::accumulator, 16, 16, 8, float> c[MF][2];
#pragma unroll
    for (int i = 0; i < MF; i++)
#pragma unroll
        for (int j = 0; j < 2; j++)
            wmma::fill_fragment(c[i][j], 0.0f);

    auto issue = [&](int kb, int st) {
        const int k0 = kb * BK;
        float* As = Asb + st * BM * LDA_S;
        float* Bs = Bsb + st * BK * LDB_S;
#pragma unroll
        for (int i = 0; i < BM / 32; i++) {          // A: BM x 32 floats
            int v = tid + i * 256;
            int r = v >> 3, cv = (v & 7) << 2;
            cp_async16(&As[r * LDA_S + cv], &A[(size_t)(bm + r) * lda + k0 + cv]);
        }
#pragma unroll
        for (int i = 0; i < 4; i++) {                // B: 32 x 128 floats
            int v = tid + i * 256;
            int r = v >> 5, cv = (v & 31) << 2;
            cp_async16(&Bs[r * LDB_S + cv], &B[(size_t)(k0 + r) * ldb + bn + cv]);
        }
        cp_commit();
    };

    const int nkb = K / BK;
    issue(0, 0);
    for (int kb = 0; kb < nkb; kb++) {
        const int st = kb & 1;
        if (kb + 1 < nkb) { issue(kb + 1, st ^ 1); cp_wait<1>(); }
        else              { cp_wait<0>(); }
        __syncthreads();

        const float* As = Asb + st * BM * LDA_S;
        const float* Bs = Bsb + st * BK * LDB_S;
#pragma unroll
        for (int kk = 0; kk < BK / 8; kk++) {
            wmma::fragment<wmma::matrix_a, 16, 16, 8, wmma::precision::tf32, wmma::row_major> a[MF];
            wmma::fragment<wmma::matrix_b, 16, 16, 8, wmma::precision::tf32, wmma::row_major> b[2];
#pragma unroll
            for (int i = 0; i < MF; i++) {
                wmma::load_matrix_sync(a[i], &As[(wrow * WM + i * 16) * LDA_S + kk * 8], LDA_S);
#pragma unroll
                for (int t = 0; t < a[i].num_elements; t++)
                    a[i].x[t] = wmma::__float_to_tf32(a[i].x[t]);
            }
#pragma unroll
            for (int j = 0; j < 2; j++) {
                wmma::load_matrix_sync(b[j], &Bs[(kk * 8) * LDB_S + wcol * 32 + j * 16], LDB_S);
#pragma unroll
                for (int t = 0; t < b[j].num_elements; t++)
                    b[j].x[t] = wmma::__float_to_tf32(b[j].x[t]);
            }
#pragma unroll
            for (int i = 0; i < MF; i++)
#pragma unroll
                for (int j = 0; j < 2; j++)
                    wmma::mma_sync(c[i][j], a[i], b[j], c[i][j]);
        }
        __syncthreads();
    }

    // Epilogue: per-warp smem staging (reuse As region), bias add, float4 stores.
    float* stage = Asb + wid * (16 * 20);
#pragma unroll
    for (int i = 0; i < MF; i++)
#pragma unroll
        for (int j = 0; j < 2; j++) {
            wmma::store_matrix_sync(stage, c[i][j], 20, wmma::mem_row_major);
            __syncwarp();
            int r  = lane >> 1;
            int cs = (lane & 1) << 3;
            int gr = bm + wrow * WM + i * 16 + r;
            int gc = bn + wcol * 32 + j * 16 + cs;
            float4 v0 = *reinterpret_cast<float4*>(&stage[r * 20 + cs]);
            float4 v1 = *reinterpret_cast<float4*>(&stage[r * 20 + cs + 4]);
            if (bias) {
                float4 b0 = *reinterpret_cast<const float4*>(&bias[gc]);
                float4 b1 = *reinterpret_cast<const float4*>(&bias[gc + 4]);
                v0.x += b0.x; v0.y += b0.y; v0.z += b0.z; v0.w += b0.w;
                v1.x += b1.x; v1.y += b1.y; v1.z += b1.z; v1.w += b1.w;
            }
            *reinterpret_cast<float4*>(&C[(size_t)gr * ldc + gc])     = v0;
            *reinterpret_cast<float4*>(&C[(size_t)gr * ldc + gc + 4]) = v1;
            __syncwarp();
        }
}

// b'[j] = sum_k b_qkv[2048+k]*w_proj[k,j] + b_proj[j].  32 blocks x 256 thr,
// 8 k-lanes x 32 cols per block, coalesced w_proj reads, smem reduce.
__global__ void bias_combine(const float* __restrict__ bq,
                             const float* __restrict__ wp,
                             const float* __restrict__ bp,
                             float* __restrict__ out)
{
    __shared__ float red[8][33];
    const int jl = threadIdx.x & 31;
    const int kl = threadIdx.x >> 5;
    const int j  = blockIdx.x * 32 + jl;
    float s = 0.0f;
    for (int k = kl; k < DIMC; k += 8)
        s = fmaf(bq[2 * DIMC + k], wp[(size_t)k * DIMC + j], s);
    red[kl][jl] = s;
    __syncthreads();
    if (kl == 0) {
        float t = bp[j];
#pragma unroll
        for (int r = 0; r < 8; r++) t += red[r][jl];
        out[j] = t;
    }
}

extern "C" void kernel_launch(void* const* d_in, const int* in_sizes, int n_in,
                              void* d_out, int out_size)
{
    const float* x      = (const float*)d_in[0];
    const float* w_qkv  = (const float*)d_in[1];
    const float* b_qkv  = (const float*)d_in[2];
    const float* w_proj = (const float*)d_in[3];
    const float* b_proj = (const float*)d_in[4];
    float* out = (float*)d_out;

    float *wc = nullptr, *bc = nullptr;
    cudaGetSymbolAddress((void**)&wc, g_wc);
    cudaGetSymbolAddress((void**)&bc, g_bc);

    constexpr int SMEM64  = (2 * 64  * (BK + 4) + 2 * BK * (BN + 4)) * 4;  // 52224
    constexpr int SMEM128 = (2 * 128 * (BK + 4) + 2 * BK * (BN + 4)) * 4;  // 70656
    static bool attr_done = false;
    if (!attr_done) {
        cudaFuncSetAttribute(gemm_tf32<64>,  cudaFuncAttributeMaxDynamicSharedMemorySize, SMEM64);
        cudaFuncSetAttribute(gemm_tf32<128>, cudaFuncAttributeMaxDynamicSharedMemorySize, SMEM128);
        attr_done = true;
    }

    // 1) W' = Wv @ Wproj  (128 CTAs for better chip coverage)
    gemm_tf32<64><<<dim3(DIMC / BN, DIMC / 64), 256, SMEM64>>>(
        w_qkv + 2 * DIMC, 3 * DIMC, w_proj, DIMC, wc, DIMC, nullptr, DIMC);

    // 2) combined bias
    bias_combine<<<DIMC / 32, 256>>>(b_qkv, w_proj, b_proj, bc);

    // 3) out = x @ W' + b'
    gemm_tf32<128><<<dim3(DIMC / BN, MX / 128), 256, SMEM128>>>(
        x, DIMC, wc, DIMC, out, DIMC, bc, DIMC);
}

// round 4
// speedup vs baseline: 1.0068x; 1.0068x over previous
#include <cuda_runtime.h>
#include <cstdint>
#include <mma.h>
using namespace nvcuda;

// Algebraic collapse: einsum('bnqk,bnqe->bnqe', softmax(attn), v) = v (softmax rows sum to 1)
// => out = (x @ Wv + b_v) @ Wproj + b_proj,  Wv = w_qkv[:, 2048:3072]
// Two identical-shape GEMMs 4096x1024x1024 -> 256 CTAs each, full chip.

constexpr int DIMC = 1024;
constexpr int MX   = 4096;               // BATCH*SEQ
constexpr int BM = 128, BN = 128, BK = 32;
constexpr int STAGES = 3;
constexpr int LDA_S = BK + 4;            // 36
constexpr int LDB_S = BN + 4;            // 132
constexpr int ASZ = BM * LDA_S;          // 4608 floats / stage
constexpr int BSZ = BK * LDB_S;          // 4224 floats / stage
constexpr int SMEM_BYTES = STAGES * (ASZ + BSZ) * 4;  // 105984

__device__ float g_T[MX * DIMC];         // intermediate T = x@Wv + b_v (tf32-rounded)

__device__ __forceinline__ void cp_async16(void* smem, const void* gmem) {
    unsigned s = (unsigned)__cvta_generic_to_shared(smem);
    asm volatile("cp.async.cg.shared.global [%0], [%1], 16;\n" :: "r"(s), "l"(gmem));
}
__device__ __forceinline__ void cp_commit() { asm volatile("cp.async.commit_group;\n"); }
template<int N> __device__ __forceinline__ void cp_wait() {
    asm volatile("cp.async.wait_group %0;\n" :: "n"(N));
}

// C[M,N] = A[M,K](lda) @ B[K,N](ldb) + bias.  512 thr, 4x4 warp grid (32x32/warp),
// 3-stage cp.async. CVT_A: round A frags to tf32 (skip when A pre-rounded).
// ROUND_OUT: store output rounded to tf32.
template<bool CVT_A, bool ROUND_OUT>
__global__ __launch_bounds__(512) void gemm_tf32(
    const float* __restrict__ A, int lda,
    const float* __restrict__ B, int ldb,
    float* __restrict__ C, int ldc,
    const float* __restrict__ bias, int K)
{
    extern __shared__ float sm[];
    float* Asb = sm;                   // [STAGES][BM][LDA_S]
    float* Bsb = sm + STAGES * ASZ;    // [STAGES][BK][LDB_S]

    const int tid  = threadIdx.x;
    const int wid  = tid >> 5;
    const int lane = tid & 31;
    const int wrow = wid >> 2;         // 0..3
    const int wcol = wid & 3;          // 0..3
    const int bm   = blockIdx.y * BM;
    const int bn   = blockIdx.x * BN;
    const int nkb  = K / BK;

    wmma::fragment<wmma::accumulator, 16, 16, 8, float> c[2][2];
#pragma unroll
    for (int i = 0; i < 2; i++)
#pragma unroll
        for (int j = 0; j < 2; j++)
            wmma::fill_fragment(c[i][j], 0.0f);

    auto issue = [&](int kb) {
        if (kb < nkb) {
            const int k0 = kb * BK;
            const int st = kb % STAGES;
            float* As = Asb + st * ASZ;
            float* Bs = Bsb + st * BSZ;
#pragma unroll
            for (int i = 0; i < 2; i++) {            // A: 128x32 = 1024 float4
                int v = tid + i * 512;
                int r = v >> 3, cv = (v & 7) << 2;
                cp_async16(&As[r * LDA_S + cv], &A[(size_t)(bm + r) * lda + k0 + cv]);
            }
#pragma unroll
            for (int i = 0; i < 2; i++) {            // B: 32x128 = 1024 float4
                int v = tid + i * 512;
                int r = v >> 5, cv = (v & 31) << 2;
                cp_async16(&Bs[r * LDB_S + cv], &B[(size_t)(k0 + r) * ldb + bn + cv]);
            }
        }
        cp_commit();
    };

    issue(0);
    issue(1);
    for (int kb = 0; kb < nkb; kb++) {
        cp_wait<1>();          // group kb complete (kb+1 may be in flight)
        __syncthreads();
        issue(kb + 2);         // into stage (kb+2)%3 — free since all passed compute(kb-1)

        const float* As = Asb + (kb % STAGES) * ASZ;
        const float* Bs = Bsb + (kb % STAGES) * BSZ;
#pragma unroll
        for (int kk = 0; kk < BK / 8; kk++) {
            wmma::fragment<wmma::matrix_a, 16, 16, 8, wmma::precision::tf32, wmma::row_major> a[2];
            wmma::fragment<wmma::matrix_b, 16, 16, 8, wmma::precision::tf32, wmma::row_major> b[2];
#pragma unroll
            for (int i = 0; i < 2; i++) {
                wmma::load_matrix_sync(a[i], &As[(wrow * 32 + i * 16) * LDA_S + kk * 8], LDA_S);
                if (CVT_A)
#pragma unroll
                    for (int t = 0; t < a[i].num_elements; t++)
                        a[i].x[t] = wmma::__float_to_tf32(a[i].x[t]);
            }
#pragma unroll
            for (int j = 0; j < 2; j++) {
                wmma::load_matrix_sync(b[j], &Bs[(kk * 8) * LDB_S + wcol * 32 + j * 16], LDB_S);
#pragma unroll
                for (int t = 0; t < b[j].num_elements; t++)
                    b[j].x[t] = wmma::__float_to_tf32(b[j].x[t]);
            }
#pragma unroll
            for (int i = 0; i < 2; i++)
#pragma unroll
                for (int j = 0; j < 2; j++)
                    wmma::mma_sync(c[i][j], a[i], b[j], c[i][j]);
        }
    }
    __syncthreads();   // before smem reuse in epilogue

    // Epilogue: per-warp smem staging, bias add, optional tf32 round, float4 stores.
    float* stage = sm + wid * (16 * 20);
#pragma unroll
    for (int i = 0; i < 2; i++)
#pragma unroll
        for (int j = 0; j < 2; j++) {
            wmma::store_matrix_sync(stage, c[i][j], 20, wmma::mem_row_major);
            __syncwarp();
            int r  = lane >> 1;
            int cs = (lane & 1) << 3;
            int gr = bm + wrow * 32 + i * 16 + r;
            int gc = bn + wcol * 32 + j * 16 + cs;
            float4 v0 = *reinterpret_cast<float4*>(&stage[r * 20 + cs]);
            float4 v1 = *reinterpret_cast<float4*>(&stage[r * 20 + cs + 4]);
            float4 b0 = *reinterpret_cast<const float4*>(&bias[gc]);
            float4 b1 = *reinterpret_cast<const float4*>(&bias[gc + 4]);
            v0.x += b0.x; v0.y += b0.y; v0.z += b0.z; v0.w += b0.w;
            v1.x += b1.x; v1.y += b1.y; v1.z += b1.z; v1.w += b1.w;
            if (ROUND_OUT) {
                v0.x = wmma::__float_to_tf32(v0.x); v0.y = wmma::__float_to_tf32(v0.y);
                v0.z = wmma::__float_to_tf32(v0.z); v0.w = wmma::__float_to_tf32(v0.w);
                v1.x = wmma::__float_to_tf32(v1.x); v1.y = wmma::__float_to_tf32(v1.y);
                v1.z = wmma::__float_to_tf32(v1.z); v1.w = wmma::__float_to_tf32(v1.w);
            }
            *reinterpret_cast<float4*>(&C[(size_t)gr * ldc + gc])     = v0;
            *reinterpret_cast<float4*>(&C[(size_t)gr * ldc + gc + 4]) = v1;
            __syncwarp();
        }
}

extern "C" void kernel_launch(void* const* d_in, const int* in_sizes, int n_in,
                              void* d_out, int out_size)
{
    const float* x      = (const float*)d_in[0];
    const float* w_qkv  = (const float*)d_in[1];
    const float* b_qkv  = (const float*)d_in[2];
    const float* w_proj = (const float*)d_in[3];
    const float* b_proj = (const float*)d_in[4];
    float* out = (float*)d_out;

    float* T = nullptr;
    cudaGetSymbolAddress((void**)&T, g_T);

    cudaFuncSetAttribute(gemm_tf32<true,  true>,
                         cudaFuncAttributeMaxDynamicSharedMemorySize, SMEM_BYTES);
    cudaFuncSetAttribute(gemm_tf32<false, false>,
                         cudaFuncAttributeMaxDynamicSharedMemorySize, SMEM_BYTES);

    dim3 grid(DIMC / BN, MX / BM);   // (8, 32) = 256 CTAs

    // 1) T = x @ Wv + b_v   (T stored tf32-rounded)
    gemm_tf32<true, true><<<grid, 512, SMEM_BYTES>>>(
        x, DIMC, w_qkv + 2 * DIMC, 3 * DIMC, T, DIMC, b_qkv + 2 * DIMC, DIMC);

    // 2) out = T @ Wproj + b_proj   (A frags already tf32 -> no cvt)
    gemm_tf32<false, false><<<grid, 512, SMEM_BYTES>>>(
        T, DIMC, w_proj, DIMC, out, DIMC, b_proj, DIMC);
}

// round 7
// speedup vs baseline: 4.0551x; 4.0276x over previous
#include <cuda_runtime.h>
#include <cuda_fp16.h>
#include <cstdint>
#include <mma.h>
using namespace nvcuda;

// Algebraic collapse: einsum('bnqk,bnqe->bnqe', softmax(attn), v) = v (softmax rows sum to 1)
// => out = (x @ Wv + b_v) @ Wproj + b_proj,  Wv = w_qkv[:, 2048:3072]
// fp16 inputs (11-bit significand, same as tf32), fp32 accumulate.

constexpr int DIMC = 1024;
constexpr int MX   = 4096;
constexpr int BM = 128, BN = 128, BK = 32;
constexpr int LDA_H = BK + 8;          // 40 halves  (80B rows; LDSM conflict-free)
constexpr int LDB_H = BN + 8;          // 136 halves (272B rows)
constexpr int ASZ_H = BM * LDA_H;      // 5120 halves / stage
constexpr int BSZ_H = BK * LDB_H;      // 4352 halves / stage
constexpr int SMEM_BYTES = 3 * (ASZ_H + BSZ_H) * 2;   // 56832

__device__ __half g_xh[MX * DIMC];     // x in fp16
__device__ __half g_wv[DIMC * DIMC];   // Wv  [k][n] fp16
__device__ __half g_wp[DIMC * DIMC];   // Wproj [k][n] fp16
__device__ __half g_T[MX * DIMC];      // intermediate T fp16

__device__ __forceinline__ void cp_async16(void* smem, const void* gmem) {
    unsigned s = (unsigned)__cvta_generic_to_shared(smem);
    asm volatile("cp.async.cg.shared.global [%0], [%1], 16;\n" :: "r"(s), "l"(gmem));
}
__device__ __forceinline__ void cp_commit() { asm volatile("cp.async.commit_group;\n"); }
template<int N> __device__ __forceinline__ void cp_wait() {
    asm volatile("cp.async.wait_group %0;\n" :: "n"(N));
}
__device__ __forceinline__ unsigned h2_bits(__half2 h) {
    return *reinterpret_cast<unsigned*>(&h);
}

// fp32 -> fp16, 4 elems/thread. in row stride ld_in, out dense [rows, cols].
__global__ void cvt_f2h(const float* __restrict__ in, int ld_in,
                        __half* __restrict__ out, int cols)
{
    int i = blockIdx.x * blockDim.x + threadIdx.x;   // float4 index
    int per_row = cols >> 2;
    int r = i / per_row;
    int c = (i - r * per_row) << 2;
    float4 v = *reinterpret_cast<const float4*>(&in[(size_t)r * ld_in + c]);
    __half2 h01 = __floats2half2_rn(v.x, v.y);
    __half2 h23 = __floats2half2_rn(v.z, v.w);
    uint2 pk = make_uint2(h2_bits(h01), h2_bits(h23));
    *reinterpret_cast<uint2*>(&out[(size_t)r * cols + c]) = pk;
}

// C[M,N] = A[M,1024] @ B[1024,N] + bias. fp16 in, fp32 accum.
// 256 thr, warp grid 2x4, warp tile 64x32 (4x2 fp16 wmma frags), 3-stage cp.async.
// OUT_HALF: write C as fp16 (for intermediate T), else fp32.
template<bool OUT_HALF>
__global__ __launch_bounds__(256) void gemm_f16(
    const __half* __restrict__ A,
    const __half* __restrict__ B,
    const float* __restrict__ bias,
    void* __restrict__ Cv)
{
    extern __shared__ __half smh[];
    __half* Asb = smh;                     // [3][BM][LDA_H]
    __half* Bsb = smh + 3 * ASZ_H;         // [3][BK][LDB_H]

    const int tid  = threadIdx.x;
    const int wid  = tid >> 5;
    const int lane = tid & 31;
    const int wrow = wid >> 2;             // 0..1
    const int wcol = wid & 3;              // 0..3
    const int bm   = blockIdx.y * BM;
    const int bn   = blockIdx.x * BN;
    constexpr int NKB = DIMC / BK;         // 32

    wmma::fragment<wmma::accumulator, 16, 16, 16, float> c[4][2];
#pragma unroll
    for (int i = 0; i < 4; i++)
#pragma unroll
        for (int j = 0; j < 2; j++)
            wmma::fill_fragment(c[i][j], 0.0f);

    auto issue = [&](int kb) {
        if (kb < NKB) {
            const int k0 = kb * BK;
            const int st = kb % 3;
            __half* As = Asb + st * ASZ_H;
            __half* Bs = Bsb + st * BSZ_H;
#pragma unroll
            for (int i = 0; i < 2; i++) {            // A: 128 rows x 4 chunks(8h)
                int v = tid + i * 256;               // 0..511
                int r = v >> 2, ch = (v & 3) << 3;
                cp_async16(&As[r * LDA_H + ch], &A[(size_t)(bm + r) * DIMC + k0 + ch]);
            }
#pragma unroll
            for (int i = 0; i < 2; i++) {            // B: 32 rows x 16 chunks(8h)
                int v = tid + i * 256;
                int r = v >> 4, ch = (v & 15) << 3;
                cp_async16(&Bs[r * LDB_H + ch], &B[(size_t)(k0 + r) * DIMC + bn + ch]);
            }
        }
        cp_commit();
    };

    issue(0);
    issue(1);
    for (int kb = 0; kb < NKB; kb++) {
        cp_wait<1>();
        __syncthreads();
        issue(kb + 2);

        const __half* As = Asb + (kb % 3) * ASZ_H;
        const __half* Bs = Bsb + (kb % 3) * BSZ_H;
#pragma unroll
        for (int kk = 0; kk < BK / 16; kk++) {
            wmma::fragment<wmma::matrix_a, 16, 16, 16, __half, wmma::row_major> a[4];
            wmma::fragment<wmma::matrix_b, 16, 16, 16, __half, wmma::row_major> b[2];
#pragma unroll
            for (int i = 0; i < 4; i++)
                wmma::load_matrix_sync(a[i], &As[(wrow * 64 + i * 16) * LDA_H + kk * 16], LDA_H);
#pragma unroll
            for (int j = 0; j < 2; j++)
                wmma::load_matrix_sync(b[j], &Bs[(kk * 16) * LDB_H + wcol * 32 + j * 16], LDB_H);
#pragma unroll
            for (int i = 0; i < 4; i++)
#pragma unroll
                for (int j = 0; j < 2; j++)
                    wmma::mma_sync(c[i][j], a[i], b[j], c[i][j]);
        }
    }
    __syncthreads();   // before smem reuse by epilogue stage

    // Epilogue: per-warp fp32 staging (16x16, ld 20), bias add, wide stores.
    float* stage = reinterpret_cast<float*>(smh) + wid * (16 * 20);
#pragma unroll
    for (int i = 0; i < 4; i++)
#pragma unroll
        for (int j = 0; j < 2; j++) {
            wmma::store_matrix_sync(stage, c[i][j], 20, wmma::mem_row_major);
            __syncwarp();
            int r  = lane >> 1;
            int cs = (lane & 1) << 3;
            int gr = bm + wrow * 64 + i * 16 + r;
            int gc = bn + wcol * 32 + j * 16 + cs;
            float4 v0 = *reinterpret_cast<float4*>(&stage[r * 20 + cs]);
            float4 v1 = *reinterpret_cast<float4*>(&stage[r * 20 + cs + 4]);
            float4 b0 = *reinterpret_cast<const float4*>(&bias[gc]);
            float4 b1 = *reinterpret_cast<const float4*>(&bias[gc + 4]);
            v0.x += b0.x; v0.y += b0.y; v0.z += b0.z; v0.w += b0.w;
            v1.x += b1.x; v1.y += b1.y; v1.z += b1.z; v1.w += b1.w;
            if (OUT_HALF) {
                __half2 h0 = __floats2half2_rn(v0.x, v0.y);
                __half2 h1 = __floats2half2_rn(v0.z, v0.w);
                __half2 h2 = __floats2half2_rn(v1.x, v1.y);
                __half2 h3 = __floats2half2_rn(v1.z, v1.w);
                uint4 pk = make_uint4(h2_bits(h0), h2_bits(h1),
                                      h2_bits(h2), h2_bits(h3));
                *reinterpret_cast<uint4*>(&((__half*)Cv)[(size_t)gr * DIMC + gc]) = pk;
            } else {
                float* C = (float*)Cv;
                *reinterpret_cast<float4*>(&C[(size_t)gr * DIMC + gc])     = v0;
                *reinterpret_cast<float4*>(&C[(size_t)gr * DIMC + gc + 4]) = v1;
            }
            __syncwarp();
        }
}

extern "C" void kernel_launch(void* const* d_in, const int* in_sizes, int n_in,
                              void* d_out, int out_size)
{
    const float* x      = (const float*)d_in[0];
    const float* w_qkv  = (const float*)d_in[1];
    const float* b_qkv  = (const float*)d_in[2];
    const float* w_proj = (const float*)d_in[3];
    const float* b_proj = (const float*)d_in[4];
    float* out = (float*)d_out;

    __half *xh, *wv, *wp, *T;
    cudaGetSymbolAddress((void**)&xh, g_xh);
    cudaGetSymbolAddress((void**)&wv, g_wv);
    cudaGetSymbolAddress((void**)&wp, g_wp);
    cudaGetSymbolAddress((void**)&T,  g_T);

    cudaFuncSetAttribute(gemm_f16<true>,
                         cudaFuncAttributeMaxDynamicSharedMemorySize, SMEM_BYTES);
    cudaFuncSetAttribute(gemm_f16<false>,
                         cudaFuncAttributeMaxDynamicSharedMemorySize, SMEM_BYTES);

    // Conversions (vectorized, fully parallel)
    cvt_f2h<<<MX * DIMC / 4 / 256, 256>>>(x, DIMC, xh, DIMC);                  // x
    cvt_f2h<<<DIMC * DIMC / 4 / 256, 256>>>(w_qkv + 2 * DIMC, 3 * DIMC, wv, DIMC); // Wv
    cvt_f2h<<<DIMC * DIMC / 4 / 256, 256>>>(w_proj, DIMC, wp, DIMC);           // Wproj

    dim3 grid(DIMC / BN, MX / BM);   // (8, 32) = 256 CTAs

    // 1) T = xh @ wv + b_v  (fp16 out)
    gemm_f16<true><<<grid, 256, SMEM_BYTES>>>(xh, wv, b_qkv + 2 * DIMC, T);
    // 2) out = T @ wp + b_proj (fp32 out)
    gemm_f16<false><<<grid, 256, SMEM_BYTES>>>(T, wp, b_proj, out);
}

// round 9
// speedup vs baseline: 4.4871x; 1.1065x over previous
#include <cuda_runtime.h>
#include <cuda_fp16.h>
#include <cstdint>
#include <mma.h>
using namespace nvcuda;

// Algebraic collapse: einsum('bnqk,bnqe->bnqe', softmax(attn), v) = v (rows sum to 1)
// => out = x @ W' + bc,  W' = Wv @ Wproj (fp16), bc = b_v @ Wproj + b_proj
// Wv = w_qkv[:, 2048:3072]. 10.7 GFLOP total, fp16 tensor cores, fp32 accum.

constexpr int DIMC = 1024;
constexpr int MX   = 4096;
constexpr int BK   = 32;
constexpr int NKB  = DIMC / BK;        // 32
constexpr int LDA_H = BK + 8;          // 40 halves

__device__ __half g_xh[MX * DIMC];
__device__ __half g_wv[DIMC * DIMC];
__device__ __half g_wp[DIMC * DIMC];
__device__ __half g_wc[DIMC * DIMC];   // W' fp16
__device__ float  g_bc[DIMC];

__device__ __forceinline__ void cp_async16(void* smem, const void* gmem) {
    unsigned s = (unsigned)__cvta_generic_to_shared(smem);
    asm volatile("cp.async.cg.shared.global [%0], [%1], 16;\n" :: "r"(s), "l"(gmem));
}
__device__ __forceinline__ void cp_commit() { asm volatile("cp.async.commit_group;\n"); }
template<int N> __device__ __forceinline__ void cp_wait() {
    asm volatile("cp.async.wait_group %0;\n" :: "n"(N));
}
__device__ __forceinline__ unsigned h2_bits(__half2 h) {
    return *reinterpret_cast<unsigned*>(&h);
}

// fp32 -> fp16, 4 elems/thread.
__global__ void cvt_f2h(const float* __restrict__ in, int ld_in,
                        __half* __restrict__ out, int cols)
{
    int i = blockIdx.x * blockDim.x + threadIdx.x;
    int per_row = cols >> 2;
    int r = i / per_row;
    int c = (i - r * per_row) << 2;
    float4 v = *reinterpret_cast<const float4*>(&in[(size_t)r * ld_in + c]);
    __half2 h01 = __floats2half2_rn(v.x, v.y);
    __half2 h23 = __floats2half2_rn(v.z, v.w);
    *reinterpret_cast<uint2*>(&out[(size_t)r * cols + c]) =
        make_uint2(h2_bits(h01), h2_bits(h23));
}

// C[TBM,TBN] tile = A[.,1024] @ B[1024,.] (+bias). fp16 in, fp32 accum.
// WRxWC warp grid, 3-stage cp.async. All row strides = 1024.
template<int TBM, int TBN, int TTHR, int WR, int WC, bool OUT_HALF>
__global__ __launch_bounds__(TTHR) void gemm_f16(
    const __half* __restrict__ A,
    const __half* __restrict__ B,
    const float* __restrict__ bias,   // may be null
    void* __restrict__ Cv)
{
    constexpr int LDB_H = TBN + 8;
    constexpr int ASZ = TBM * LDA_H;
    constexpr int BSZ = BK * LDB_H;
    constexpr int MF  = (TBM / WR) / 16;
    constexpr int NF  = (TBN / WC) / 16;
    constexpr int AC  = TBM * 4;          // 16B chunks in A tile
    constexpr int BC  = TBN * 4;          // 16B chunks in B tile

    extern __shared__ __half smh[];
    __half* Asb = smh;
    __half* Bsb = smh + 3 * ASZ;

    const int tid  = threadIdx.x;
    const int wid  = tid >> 5;
    const int lane = tid & 31;
    const int wrow = wid / WC;
    const int wcol = wid % WC;
    const int bm   = blockIdx.y * TBM;
    const int bn   = blockIdx.x * TBN;

    wmma::fragment<wmma::accumulator, 16, 16, 16, float> c[MF][NF];
#pragma unroll
    for (int i = 0; i < MF; i++)
#pragma unroll
        for (int j = 0; j < NF; j++)
            wmma::fill_fragment(c[i][j], 0.0f);

    auto issue = [&](int kb) {
        if (kb < NKB) {
            const int k0 = kb * BK;
            const int st = kb % 3;
            __half* As = Asb + st * ASZ;
            __half* Bs = Bsb + st * BSZ;
#pragma unroll
            for (int i = 0; i < (AC + TTHR - 1) / TTHR; i++) {
                int v = tid + i * TTHR;
                if (AC % TTHR == 0 || v < AC) {
                    int r = v >> 2, ch = (v & 3) << 3;
                    cp_async16(&As[r * LDA_H + ch], &A[(size_t)(bm + r) * DIMC + k0 + ch]);
                }
            }
#pragma unroll
            for (int i = 0; i < (BC + TTHR - 1) / TTHR; i++) {
                int v = tid + i * TTHR;
                if (BC % TTHR == 0 || v < BC) {
                    int r = v / (TBN / 8), ch = (v % (TBN / 8)) << 3;
                    cp_async16(&Bs[r * LDB_H + ch], &B[(size_t)(k0 + r) * DIMC + bn + ch]);
                }
            }
        }
        cp_commit();
    };

    issue(0);
    issue(1);
    for (int kb = 0; kb < NKB; kb++) {
        cp_wait<1>();
        __syncthreads();
        issue(kb + 2);

        const __half* As = Asb + (kb % 3) * ASZ;
        const __half* Bs = Bsb + (kb % 3) * BSZ;
#pragma unroll
        for (int kk = 0; kk < BK / 16; kk++) {
            wmma::fragment<wmma::matrix_a, 16, 16, 16, __half, wmma::row_major> a[MF];
            wmma::fragment<wmma::matrix_b, 16, 16, 16, __half, wmma::row_major> b[NF];
#pragma unroll
            for (int i = 0; i < MF; i++)
                wmma::load_matrix_sync(a[i],
                    &As[(wrow * (TBM / WR) + i * 16) * LDA_H + kk * 16], LDA_H);
#pragma unroll
            for (int j = 0; j < NF; j++)
                wmma::load_matrix_sync(b[j],
                    &Bs[(kk * 16) * LDB_H + wcol * (TBN / WC) + j * 16], LDB_H);
#pragma unroll
            for (int i = 0; i < MF; i++)
#pragma unroll
                for (int j = 0; j < NF; j++)
                    wmma::mma_sync(c[i][j], a[i], b[j], c[i][j]);
        }
    }
    __syncthreads();

    // Epilogue: per-warp fp32 staging (16 rows, ld 20), optional bias, wide stores.
    float* stage = reinterpret_cast<float*>(smh) + wid * (16 * 20);
#pragma unroll
    for (int i = 0; i < MF; i++)
#pragma unroll
        for (int j = 0; j < NF; j++) {
            wmma::store_matrix_sync(stage, c[i][j], 20, wmma::mem_row_major);
            __syncwarp();
            int r  = lane >> 1;
            int cs = (lane & 1) << 3;
            int gr = bm + wrow * (TBM / WR) + i * 16 + r;
            int gc = bn + wcol * (TBN / WC) + j * 16 + cs;
            float4 v0 = *reinterpret_cast<float4*>(&stage[r * 20 + cs]);
            float4 v1 = *reinterpret_cast<float4*>(&stage[r * 20 + cs + 4]);
            if (bias) {
                float4 b0 = *reinterpret_cast<const float4*>(&bias[gc]);
                float4 b1 = *reinterpret_cast<const float4*>(&bias[gc + 4]);
                v0.x += b0.x; v0.y += b0.y; v0.z += b0.z; v0.w += b0.w;
                v1.x += b1.x; v1.y += b1.y; v1.z += b1.z; v1.w += b1.w;
            }
            if (OUT_HALF) {
                __half2 h0 = __floats2half2_rn(v0.x, v0.y);
                __half2 h1 = __floats2half2_rn(v0.z, v0.w);
                __half2 h2 = __floats2half2_rn(v1.x, v1.y);
                __half2 h3 = __floats2half2_rn(v1.z, v1.w);
                *reinterpret_cast<uint4*>(&((__half*)Cv)[(size_t)gr * DIMC + gc]) =
                    make_uint4(h2_bits(h0), h2_bits(h1), h2_bits(h2), h2_bits(h3));
            } else {
                float* C = (float*)Cv;
                *reinterpret_cast<float4*>(&C[(size_t)gr * DIMC + gc])     = v0;
                *reinterpret_cast<float4*>(&C[(size_t)gr * DIMC + gc + 4]) = v1;
            }
            __syncwarp();
        }
}

// bc[j] = sum_k b_qkv[2048+k]*w_proj[k,j] + b_proj[j]
__global__ void bias_combine(const float* __restrict__ bq,
                             const float* __restrict__ wp,
                             const float* __restrict__ bp,
                             float* __restrict__ out)
{
    __shared__ float red[8][33];
    const int jl = threadIdx.x & 31;
    const int kl = threadIdx.x >> 5;
    const int j  = blockIdx.x * 32 + jl;
    float s = 0.0f;
    for (int k = kl; k < DIMC; k += 8)
        s = fmaf(bq[2 * DIMC + k], wp[(size_t)k * DIMC + j], s);
    red[kl][jl] = s;
    __syncthreads();
    if (kl == 0) {
        float t = bp[j];
#pragma unroll
        for (int r = 0; r < 8; r++) t += red[r][jl];
        out[j] = t;
    }
}

extern "C" void kernel_launch(void* const* d_in, const int* in_sizes, int n_in,
                              void* d_out, int out_size)
{
    const float* x      = (const float*)d_in[0];
    const float* w_qkv  = (const float*)d_in[1];
    const float* b_qkv  = (const float*)d_in[2];
    const float* w_proj = (const float*)d_in[3];
    const float* b_proj = (const float*)d_in[4];
    float* out = (float*)d_out;

    __half *xh, *wv, *wp, *wc;
    float* bc;
    cudaGetSymbolAddress((void**)&xh, g_xh);
    cudaGetSymbolAddress((void**)&wv, g_wv);
    cudaGetSymbolAddress((void**)&wp, g_wp);
    cudaGetSymbolAddress((void**)&wc, g_wc);
    cudaGetSymbolAddress((void**)&bc, g_bc);

    // Weight GEMM: 64x128 tiles, 256 thr, 2x4 warps (32x32/warp), grid 128
    constexpr int SMW = 3 * (64 * LDA_H + BK * (128 + 8)) * 2;    // 41472
    // Main GEMM: 128x256 tiles, 512 thr, 2x8 warps (64x32/warp), grid 128
    constexpr int SMM = 3 * (128 * LDA_H + BK * (256 + 8)) * 2;   // 81408
    cudaFuncSetAttribute((gemm_f16<64, 128, 256, 2, 4, true>),
                         cudaFuncAttributeMaxDynamicSharedMemorySize, SMW);
    cudaFuncSetAttribute((gemm_f16<128, 256, 512, 2, 8, false>),
                         cudaFuncAttributeMaxDynamicSharedMemorySize, SMM);

    cvt_f2h<<<MX * DIMC / 1024, 256>>>(x, DIMC, xh, DIMC);
    cvt_f2h<<<DIMC * DIMC / 1024, 256>>>(w_qkv + 2 * DIMC, 3 * DIMC, wv, DIMC);
    cvt_f2h<<<DIMC * DIMC / 1024, 256>>>(w_proj, DIMC, wp, DIMC);

    // W' = Wv @ Wproj  (fp16 out), grid (8,16)=128 CTAs
    gemm_f16<64, 128, 256, 2, 4, true>
        <<<dim3(DIMC / 128, DIMC / 64), 256, SMW>>>(wv, wp, nullptr, wc);

    bias_combine<<<DIMC / 32, 256>>>(b_qkv, w_proj, b_proj, bc);

    // out = x @ W' + bc, grid (4,32)=128 CTAs, single wave
    gemm_f16<128, 256, 512, 2, 8, false>
        <<<dim3(DIMC / 256, MX / 128), 512, SMM>>>(xh, wc, bc, out);
}

// round 10
// speedup vs baseline: 4.8904x; 1.0899x over previous
#include <cuda_runtime.h>
#include <cuda_fp16.h>
#include <cstdint>
#include <mma.h>
using namespace nvcuda;

// Algebraic collapse: einsum('bnqk,bnqe->bnqe', softmax(attn), v) = v (rows sum to 1)
// => out = x @ W' + bc,  W' = Wv @ Wproj (fp16), bc = b_v @ Wproj + b_proj
// Wv = w_qkv[:, 2048:3072]. 10.7 GFLOP total, fp16 tensor cores, fp32 accum.

constexpr int DIMC = 1024;
constexpr int MX   = 4096;

__device__ __half g_xh[MX * DIMC];
__device__ __half g_wv[DIMC * DIMC];
__device__ __half g_wp[DIMC * DIMC];
__device__ __half g_wc[DIMC * DIMC];   // W' fp16
__device__ float  g_bc[DIMC];

__device__ __forceinline__ void cp_async16(void* smem, const void* gmem) {
    unsigned s = (unsigned)__cvta_generic_to_shared(smem);
    asm volatile("cp.async.cg.shared.global [%0], [%1], 16;\n" :: "r"(s), "l"(gmem));
}
__device__ __forceinline__ void cp_commit() { asm volatile("cp.async.commit_group;\n"); }
template<int N> __device__ __forceinline__ void cp_wait() {
    asm volatile("cp.async.wait_group %0;\n" :: "n"(N));
}
__device__ __forceinline__ unsigned h2_bits(__half2 h) {
    return *reinterpret_cast<unsigned*>(&h);
}

// One fused conversion kernel: x (dense), Wv (strided src), Wproj (dense).
// One float4 per thread.
__global__ void cvt_all(const float* __restrict__ x,
                        const float* __restrict__ wqkv,
                        const float* __restrict__ wproj,
                        __half* __restrict__ xh,
                        __half* __restrict__ wv,
                        __half* __restrict__ wp)
{
    constexpr int XN = MX * DIMC / 4;       // 1M float4
    constexpr int WN = DIMC * DIMC / 4;     // 256K float4
    int i = blockIdx.x * blockDim.x + threadIdx.x;
    float4 v;
    __half* dst;
    size_t didx;
    if (i < XN) {
        v = *reinterpret_cast<const float4*>(&x[(size_t)i * 4]);
        dst = xh; didx = (size_t)i * 4;
    } else if (i < XN + WN) {
        int j = i - XN;
        int r = j >> 8;                       // 256 float4 per row
        int c = (j & 255) << 2;
        v = *reinterpret_cast<const float4*>(&wqkv[(size_t)r * 3 * DIMC + 2 * DIMC + c]);
        dst = wv; didx = (size_t)r * DIMC + c;
    } else {
        int j = i - XN - WN;
        v = *reinterpret_cast<const float4*>(&wproj[(size_t)j * 4]);
        dst = wp; didx = (size_t)j * 4;
    }
    __half2 h01 = __floats2half2_rn(v.x, v.y);
    __half2 h23 = __floats2half2_rn(v.z, v.w);
    *reinterpret_cast<uint2*>(&dst[didx]) = make_uint2(h2_bits(h01), h2_bits(h23));
}

// C[TBM,TBN] tile = A[.,1024] @ B[1024,.] (+bias). fp16 in, fp32 accum.
// WRxWC warp grid, STAGES-deep cp.async pipeline, K-block depth BK.
template<int TBM, int TBN, int TTHR, int WR, int WC, int BK, int STAGES, bool OUT_HALF>
__global__ __launch_bounds__(TTHR) void gemm_f16(
    const __half* __restrict__ A,
    const __half* __restrict__ B,
    const float* __restrict__ bias,   // may be null
    void* __restrict__ Cv)
{
    constexpr int NKB   = DIMC / BK;
    constexpr int LDA_H = BK + 8;
    constexpr int LDB_H = TBN + 8;
    constexpr int ASZ = TBM * LDA_H;
    constexpr int BSZ = BK * LDB_H;
    constexpr int MF  = (TBM / WR) / 16;
    constexpr int NF  = (TBN / WC) / 16;
    constexpr int ACP = BK / 8;           // A 16B-chunks per row
    constexpr int BCP = TBN / 8;          // B 16B-chunks per row
    constexpr int AC  = TBM * ACP;
    constexpr int BC  = BK * BCP;

    extern __shared__ __half smh[];
    __half* Asb = smh;
    __half* Bsb = smh + STAGES * ASZ;

    const int tid  = threadIdx.x;
    const int wid  = tid >> 5;
    const int lane = tid & 31;
    const int wrow = wid / WC;
    const int wcol = wid % WC;
    const int bm   = blockIdx.y * TBM;
    const int bn   = blockIdx.x * TBN;

    wmma::fragment<wmma::accumulator, 16, 16, 16, float> c[MF][NF];
#pragma unroll
    for (int i = 0; i < MF; i++)
#pragma unroll
        for (int j = 0; j < NF; j++)
            wmma::fill_fragment(c[i][j], 0.0f);

    auto issue = [&](int kb) {
        if (kb < NKB) {
            const int k0 = kb * BK;
            const int st = kb % STAGES;
            __half* As = Asb + st * ASZ;
            __half* Bs = Bsb + st * BSZ;
#pragma unroll
            for (int i = 0; i < AC / TTHR; i++) {
                int v = tid + i * TTHR;
                int r = v / ACP, ch = (v % ACP) << 3;
                cp_async16(&As[r * LDA_H + ch], &A[(size_t)(bm + r) * DIMC + k0 + ch]);
            }
#pragma unroll
            for (int i = 0; i < BC / TTHR; i++) {
                int v = tid + i * TTHR;
                int r = v / BCP, ch = (v % BCP) << 3;
                cp_async16(&Bs[r * LDB_H + ch], &B[(size_t)(k0 + r) * DIMC + bn + ch]);
            }
        }
        cp_commit();
    };

    auto compute = [&](int kb) {
        const __half* As = Asb + (kb % STAGES) * ASZ;
        const __half* Bs = Bsb + (kb % STAGES) * BSZ;
#pragma unroll
        for (int kk = 0; kk < BK / 16; kk++) {
            wmma::fragment<wmma::matrix_a, 16, 16, 16, __half, wmma::row_major> a[MF];
            wmma::fragment<wmma::matrix_b, 16, 16, 16, __half, wmma::row_major> b[NF];
#pragma unroll
            for (int i = 0; i < MF; i++)
                wmma::load_matrix_sync(a[i],
                    &As[(wrow * (TBM / WR) + i * 16) * LDA_H + kk * 16], LDA_H);
#pragma unroll
            for (int j = 0; j < NF; j++)
                wmma::load_matrix_sync(b[j],
                    &Bs[(kk * 16) * LDB_H + wcol * (TBN / WC) + j * 16], LDB_H);
#pragma unroll
            for (int i = 0; i < MF; i++)
#pragma unroll
                for (int j = 0; j < NF; j++)
                    wmma::mma_sync(c[i][j], a[i], b[j], c[i][j]);
        }
    };

    issue(0);
    issue(1);
    for (int kb = 0; kb < NKB; kb++) {
        cp_wait<1>();            // group kb complete; kb+1 may be in flight
        __syncthreads();
        if (STAGES >= 3) {
            issue(kb + 2);       // stage (kb+2)%3 is free (computed 2 iters ago)
            compute(kb);
        } else {
            compute(kb);
            __syncthreads();     // stage kb%2 fully consumed
            issue(kb + 2);
        }
    }
    __syncthreads();

    // Epilogue: per-warp fp32 staging (16 rows, ld 20), optional bias, wide stores.
    float* stage = reinterpret_cast<float*>(smh) + wid * (16 * 20);
#pragma unroll
    for (int i = 0; i < MF; i++)
#pragma unroll
        for (int j = 0; j < NF; j++) {
            wmma::store_matrix_sync(stage, c[i][j], 20, wmma::mem_row_major);
            __syncwarp();
            int r  = lane >> 1;
            int cs = (lane & 1) << 3;
            int gr = bm + wrow * (TBM / WR) + i * 16 + r;
            int gc = bn + wcol * (TBN / WC) + j * 16 + cs;
            float4 v0 = *reinterpret_cast<float4*>(&stage[r * 20 + cs]);
            float4 v1 = *reinterpret_cast<float4*>(&stage[r * 20 + cs + 4]);
            if (bias) {
                float4 b0 = *reinterpret_cast<const float4*>(&bias[gc]);
                float4 b1 = *reinterpret_cast<const float4*>(&bias[gc + 4]);
                v0.x += b0.x; v0.y += b0.y; v0.z += b0.z; v0.w += b0.w;
                v1.x += b1.x; v1.y += b1.y; v1.z += b1.z; v1.w += b1.w;
            }
            if (OUT_HALF) {
                __half2 h0 = __floats2half2_rn(v0.x, v0.y);
                __half2 h1 = __floats2half2_rn(v0.z, v0.w);
                __half2 h2 = __floats2half2_rn(v1.x, v1.y);
                __half2 h3 = __floats2half2_rn(v1.z, v1.w);
                *reinterpret_cast<uint4*>(&((__half*)Cv)[(size_t)gr * DIMC + gc]) =
                    make_uint4(h2_bits(h0), h2_bits(h1), h2_bits(h2), h2_bits(h3));
            } else {
                float* C = (float*)Cv;
                *reinterpret_cast<float4*>(&C[(size_t)gr * DIMC + gc])     = v0;
                *reinterpret_cast<float4*>(&C[(size_t)gr * DIMC + gc + 4]) = v1;
            }
            __syncwarp();
        }
}

// bc[j] = sum_k b_qkv[2048+k]*w_proj[k,j] + b_proj[j]
__global__ void bias_combine(const float* __restrict__ bq,
                             const float* __restrict__ wp,
                             const float* __restrict__ bp,
                             float* __restrict__ out)
{
    __shared__ float red[8][33];
    const int jl = threadIdx.x & 31;
    const int kl = threadIdx.x >> 5;
    const int j  = blockIdx.x * 32 + jl;
    float s = 0.0f;
    for (int k = kl; k < DIMC; k += 8)
        s = fmaf(bq[2 * DIMC + k], wp[(size_t)k * DIMC + j], s);
    red[kl][jl] = s;
    __syncthreads();
    if (kl == 0) {
        float t = bp[j];
#pragma unroll
        for (int r = 0; r < 8; r++) t += red[r][jl];
        out[j] = t;
    }
}

extern "C" void kernel_launch(void* const* d_in, const int* in_sizes, int n_in,
                              void* d_out, int out_size)
{
    const float* x      = (const float*)d_in[0];
    const float* w_qkv  = (const float*)d_in[1];
    const float* b_qkv  = (const float*)d_in[2];
    const float* w_proj = (const float*)d_in[3];
    const float* b_proj = (const float*)d_in[4];
    float* out = (float*)d_out;

    __half *xh, *wv, *wp, *wc;
    float* bc;
    cudaGetSymbolAddress((void**)&xh, g_xh);
    cudaGetSymbolAddress((void**)&wv, g_wv);
    cudaGetSymbolAddress((void**)&wp, g_wp);
    cudaGetSymbolAddress((void**)&wc, g_wc);
    cudaGetSymbolAddress((void**)&bc, g_bc);

    // Weight GEMM: 64x64 tiles, 128 thr, 2x2 warps (32x32/warp), BK=32, 3 stages
    constexpr int SMW = 3 * (64 * 40 + 32 * 72) * 2;              // 29184
    // Main GEMM: 128x256 tiles, 512 thr, 2x8 warps (64x32/warp), BK=64, 2 stages
    constexpr int SMM = 2 * (128 * 72 + 64 * 264) * 2;            // 104448
    cudaFuncSetAttribute((gemm_f16<64, 64, 128, 2, 2, 32, 3, true>),
                         cudaFuncAttributeMaxDynamicSharedMemorySize, SMW);
    cudaFuncSetAttribute((gemm_f16<128, 256, 512, 2, 8, 64, 2, false>),
                         cudaFuncAttributeMaxDynamicSharedMemorySize, SMM);

    // All fp32->fp16 conversions in one launch
    constexpr int CVT_T = (MX * DIMC + 2 * DIMC * DIMC) / 4;      // 1.5M float4
    cvt_all<<<CVT_T / 256, 256>>>(x, w_qkv, w_proj, xh, wv, wp);

    // W' = Wv @ Wproj (fp16 out), grid (16,16)=256 CTAs
    gemm_f16<64, 64, 128, 2, 2, 32, 3, true>
        <<<dim3(DIMC / 64, DIMC / 64), 128, SMW>>>(wv, wp, nullptr, wc);

    bias_combine<<<DIMC / 32, 256>>>(b_qkv, w_proj, b_proj, bc);

    // out = x @ W' + bc, grid (4,32)=128 CTAs, single wave
    gemm_f16<128, 256, 512, 2, 8, 64, 2, false>
        <<<dim3(DIMC / 256, MX / 128), 512, SMM>>>(xh, wc, bc, out);
}

// round 12
// speedup vs baseline: 4.9297x; 1.0080x over previous
#include <cuda_runtime.h>
#include <cuda_fp16.h>
#include <cstdint>
#include <mma.h>
using namespace nvcuda;

// Algebraic collapse: einsum('bnqk,bnqe->bnqe', softmax(attn), v) = v (rows sum to 1)
// => out = x @ W' + bc,  W' = Wv @ Wproj (fp16), bc = b_v @ Wproj + b_proj
// Wv = w_qkv[:, 2048:3072]. 10.7 GFLOP total, fp16 tensor cores, fp32 accum.

constexpr int DIMC = 1024;
constexpr int MX   = 4096;

__device__ __half g_xh[MX * DIMC];
__device__ __half g_wv[DIMC * DIMC];
__device__ __half g_wp[DIMC * DIMC];
__device__ __half g_wc[DIMC * DIMC];   // W' fp16
__device__ float  g_bc[DIMC];

__device__ __forceinline__ void cp_async16(void* smem, const void* gmem) {
    unsigned s = (unsigned)__cvta_generic_to_shared(smem);
    asm volatile("cp.async.cg.shared.global [%0], [%1], 16;\n" :: "r"(s), "l"(gmem));
}
__device__ __forceinline__ void cp_commit() { asm volatile("cp.async.commit_group;\n"); }
template<int N> __device__ __forceinline__ void cp_wait() {
    asm volatile("cp.async.wait_group %0;\n" :: "n"(N));
}
__device__ __forceinline__ unsigned h2_bits(__half2 h) {
    return *reinterpret_cast<unsigned*>(&h);
}

// One fused conversion kernel: x (dense), Wv (strided src), Wproj (dense).
__global__ void cvt_all(const float* __restrict__ x,
                        const float* __restrict__ wqkv,
                        const float* __restrict__ wproj,
                        __half* __restrict__ xh,
                        __half* __restrict__ wv,
                        __half* __restrict__ wp)
{
    constexpr int XN = MX * DIMC / 4;
    constexpr int WN = DIMC * DIMC / 4;
    int i = blockIdx.x * blockDim.x + threadIdx.x;
    float4 v;
    __half* dst;
    size_t didx;
    if (i < XN) {
        v = *reinterpret_cast<const float4*>(&x[(size_t)i * 4]);
        dst = xh; didx = (size_t)i * 4;
    } else if (i < XN + WN) {
        int j = i - XN;
        int r = j >> 8;
        int c = (j & 255) << 2;
        v = *reinterpret_cast<const float4*>(&wqkv[(size_t)r * 3 * DIMC + 2 * DIMC + c]);
        dst = wv; didx = (size_t)r * DIMC + c;
    } else {
        int j = i - XN - WN;
        v = *reinterpret_cast<const float4*>(&wproj[(size_t)j * 4]);
        dst = wp; didx = (size_t)j * 4;
    }
    __half2 h01 = __floats2half2_rn(v.x, v.y);
    __half2 h23 = __floats2half2_rn(v.z, v.w);
    *reinterpret_cast<uint2*>(&dst[didx]) = make_uint2(h2_bits(h01), h2_bits(h23));
}

// C[TBM,TBN] tile = A[.,1024] @ B[1024,.] (+bias). fp16 in, fp32 accum.
// WRxWC warp grid, STAGES-deep cp.async pipeline, K-block depth BK.
template<int TBM, int TBN, int TTHR, int WR, int WC, int BK, int STAGES, bool OUT_HALF>
__global__ __launch_bounds__(TTHR) void gemm_f16(
    const __half* __restrict__ A,
    const __half* __restrict__ B,
    const float* __restrict__ bias,   // may be null
    void* __restrict__ Cv)
{
    constexpr int NKB   = DIMC / BK;
    constexpr int LDA_H = BK + 8;
    constexpr int LDB_H = TBN + 8;
    constexpr int ASZ = TBM * LDA_H;
    constexpr int BSZ = BK * LDB_H;
    constexpr int MF  = (TBM / WR) / 16;
    constexpr int NF  = (TBN / WC) / 16;
    constexpr int ACP = BK / 8;
    constexpr int BCP = TBN / 8;
    constexpr int AC  = TBM * ACP;
    constexpr int BC  = BK * BCP;

    extern __shared__ __half smh[];
    __half* Asb = smh;
    __half* Bsb = smh + STAGES * ASZ;

    const int tid  = threadIdx.x;
    const int wid  = tid >> 5;
    const int lane = tid & 31;
    const int wrow = wid / WC;
    const int wcol = wid % WC;
    const int bm   = blockIdx.y * TBM;
    const int bn   = blockIdx.x * TBN;

    wmma::fragment<wmma::accumulator, 16, 16, 16, float> c[MF][NF];
#pragma unroll
    for (int i = 0; i < MF; i++)
#pragma unroll
        for (int j = 0; j < NF; j++)
            wmma::fill_fragment(c[i][j], 0.0f);

    auto issue = [&](int kb) {
        if (kb < NKB) {
            const int k0 = kb * BK;
            const int st = kb % STAGES;
            __half* As = Asb + st * ASZ;
            __half* Bs = Bsb + st * BSZ;
#pragma unroll
            for (int i = 0; i < AC / TTHR; i++) {
                int v = tid + i * TTHR;
                int r = v / ACP, ch = (v % ACP) << 3;
                cp_async16(&As[r * LDA_H + ch], &A[(size_t)(bm + r) * DIMC + k0 + ch]);
            }
#pragma unroll
            for (int i = 0; i < BC / TTHR; i++) {
                int v = tid + i * TTHR;
                int r = v / BCP, ch = (v % BCP) << 3;
                cp_async16(&Bs[r * LDB_H + ch], &B[(size_t)(k0 + r) * DIMC + bn + ch]);
            }
        }
        cp_commit();
    };

    auto compute = [&](int kb) {
        const __half* As = Asb + (kb % STAGES) * ASZ;
        const __half* Bs = Bsb + (kb % STAGES) * BSZ;
#pragma unroll
        for (int kk = 0; kk < BK / 16; kk++) {
            wmma::fragment<wmma::matrix_a, 16, 16, 16, __half, wmma::row_major> a[MF];
            wmma::fragment<wmma::matrix_b, 16, 16, 16, __half, wmma::row_major> b[NF];
#pragma unroll
            for (int i = 0; i < MF; i++)
                wmma::load_matrix_sync(a[i],
                    &As[(wrow * (TBM / WR) + i * 16) * LDA_H + kk * 16], LDA_H);
#pragma unroll
            for (int j = 0; j < NF; j++)
                wmma::load_matrix_sync(b[j],
                    &Bs[(kk * 16) * LDB_H + wcol * (TBN / WC) + j * 16], LDB_H);
#pragma unroll
            for (int i = 0; i < MF; i++)
#pragma unroll
                for (int j = 0; j < NF; j++)
                    wmma::mma_sync(c[i][j], a[i], b[j], c[i][j]);
        }
    };

    issue(0);
    issue(1);
    for (int kb = 0; kb < NKB; kb++) {
        cp_wait<1>();
        __syncthreads();
        if (STAGES >= 3) {
            issue(kb + 2);
            compute(kb);
        } else {
            compute(kb);
            __syncthreads();
            issue(kb + 2);
        }
    }
    __syncthreads();

    // Epilogue: per-warp fp32 staging (16 rows, ld 20), optional bias, wide stores.
    float* stage = reinterpret_cast<float*>(smh) + wid * (16 * 20);
#pragma unroll
    for (int i = 0; i < MF; i++)
#pragma unroll
        for (int j = 0; j < NF; j++) {
            wmma::store_matrix_sync(stage, c[i][j], 20, wmma::mem_row_major);
            __syncwarp();
            int r  = lane >> 1;
            int cs = (lane & 1) << 3;
            int gr = bm + wrow * (TBM / WR) + i * 16 + r;
            int gc = bn + wcol * (TBN / WC) + j * 16 + cs;
            float4 v0 = *reinterpret_cast<float4*>(&stage[r * 20 + cs]);
            float4 v1 = *reinterpret_cast<float4*>(&stage[r * 20 + cs + 4]);
            if (bias) {
                float4 b0 = *reinterpret_cast<const float4*>(&bias[gc]);
                float4 b1 = *reinterpret_cast<const float4*>(&bias[gc + 4]);
                v0.x += b0.x; v0.y += b0.y; v0.z += b0.z; v0.w += b0.w;
                v1.x += b1.x; v1.y += b1.y; v1.z += b1.z; v1.w += b1.w;
            }
            if (OUT_HALF) {
                __half2 h0 = __floats2half2_rn(v0.x, v0.y);
                __half2 h1 = __floats2half2_rn(v0.z, v0.w);
                __half2 h2 = __floats2half2_rn(v1.x, v1.y);
                __half2 h3 = __floats2half2_rn(v1.z, v1.w);
                *reinterpret_cast<uint4*>(&((__half*)Cv)[(size_t)gr * DIMC + gc]) =
                    make_uint4(h2_bits(h0), h2_bits(h1), h2_bits(h2), h2_bits(h3));
            } else {
                float* C = (float*)Cv;
                *reinterpret_cast<float4*>(&C[(size_t)gr * DIMC + gc])     = v0;
                *reinterpret_cast<float4*>(&C[(size_t)gr * DIMC + gc + 4]) = v1;
            }
            __syncwarp();
        }
}

// bc[j] = sum_k b_qkv[2048+k]*w_proj[k,j] + b_proj[j]
__global__ void bias_combine(const float* __restrict__ bq,
                             const float* __restrict__ wp,
                             const float* __restrict__ bp,
                             float* __restrict__ out)
{
    __shared__ float red[8][33];
    const int jl = threadIdx.x & 31;
    const int kl = threadIdx.x >> 5;
    const int j  = blockIdx.x * 32 + jl;
    float s = 0.0f;
    for (int k = kl; k < DIMC; k += 8)
        s = fmaf(bq[2 * DIMC + k], wp[(size_t)k * DIMC + j], s);
    red[kl][jl] = s;
    __syncthreads();
    if (kl == 0) {
        float t = bp[j];
#pragma unroll
        for (int r = 0; r < 8; r++) t += red[r][jl];
        out[j] = t;
    }
}

extern "C" void kernel_launch(void* const* d_in, const int* in_sizes, int n_in,
                              void* d_out, int out_size)
{
    const float* x      = (const float*)d_in[0];
    const float* w_qkv  = (const float*)d_in[1];
    const float* b_qkv  = (const float*)d_in[2];
    const float* w_proj = (const float*)d_in[3];
    const float* b_proj = (const float*)d_in[4];
    float* out = (float*)d_out;

    __half *xh, *wv, *wp, *wc;
    float* bc;
    cudaGetSymbolAddress((void**)&xh, g_xh);
    cudaGetSymbolAddress((void**)&wv, g_wv);
    cudaGetSymbolAddress((void**)&wp, g_wp);
    cudaGetSymbolAddress((void**)&wc, g_wc);
    cudaGetSymbolAddress((void**)&bc, g_bc);

    // Weight GEMM: 64x64 tiles, 128 thr, 2x2 warps (32x32/warp), BK=32, 3 stages
    constexpr int SMW = 3 * (64 * 40 + 32 * 72) * 2;              // 29184
    // Main GEMM: 128x256 tiles, 256 thr, 2x4 warps (64x64/warp), BK=64, 2 stages
    constexpr int SMM = 2 * (128 * 72 + 64 * 264) * 2;            // 104448
    cudaFuncSetAttribute((gemm_f16<64, 64, 128, 2, 2, 32, 3, true>),
                         cudaFuncAttributeMaxDynamicSharedMemorySize, SMW);
    cudaFuncSetAttribute((gemm_f16<128, 256, 256, 2, 4, 64, 2, false>),
                         cudaFuncAttributeMaxDynamicSharedMemorySize, SMM);

    // All fp32->fp16 conversions in one launch
    constexpr int CVT_T = (MX * DIMC + 2 * DIMC * DIMC) / 4;
    cvt_all<<<CVT_T / 256, 256>>>(x, w_qkv, w_proj, xh, wv, wp);

    // W' = Wv @ Wproj (fp16 out), grid (16,16)=256 CTAs
    gemm_f16<64, 64, 128, 2, 2, 32, 3, true>
        <<<dim3(DIMC / 64, DIMC / 64), 128, SMW>>>(wv, wp, nullptr, wc);

    bias_combine<<<DIMC / 32, 256>>>(b_qkv, w_proj, b_proj, bc);

    // out = x @ W' + bc, grid (4,32)=128 CTAs, single wave, 64x64 warp tiles
    gemm_f16<128, 256, 256, 2, 4, 64, 2, false>
        <<<dim3(DIMC / 256, MX / 128), 256, SMM>>>(xh, wc, bc, out);
}